// round 10
// baseline (speedup 1.0000x reference)
#include <cuda_runtime.h>
#include <cstdint>

// Problem dims
#define PD1   128
#define PD2   128
#define PB    16
#define PSIN  64
#define PSOUT 128
// a / h layout: [i][j][b][s] row-major, s fastest.
// float offset = i*262144 + j*2048 + b*128 + s

// ---------------- helpers ----------------
__device__ __forceinline__ float tanh_mufu(float z) {
    float r;
    asm("tanh.approx.f32 %0, %1;" : "=f"(r) : "f"(z));
    return r;
}
// split fp32 into tf32 hi + tf32 lo (3xTF32 trick)
__device__ __forceinline__ void split_tf32(float x, uint32_t &hi, uint32_t &lo) {
    asm("cvt.rna.tf32.f32 %0, %1;" : "=r"(hi) : "f"(x));
    float r = x - __uint_as_float(hi);
    asm("cvt.rna.tf32.f32 %0, %1;" : "=r"(lo) : "f"(r));
}
__device__ __forceinline__ void mma16n8k8(float* d, const uint32_t* a,
                                          uint32_t b0, uint32_t b1) {
    asm("mma.sync.aligned.m16n8k8.row.col.f32.tf32.tf32.f32 "
        "{%0,%1,%2,%3}, {%4,%5,%6,%7}, {%8,%9}, {%0,%1,%2,%3};"
        : "+f"(d[0]), "+f"(d[1]), "+f"(d[2]), "+f"(d[3])
        : "r"(a[0]), "r"(a[1]), "r"(a[2]), "r"(a[3]), "r"(b0), "r"(b1));
}

// ---------------- Kernel 1: a = x @ w + bias via 3xTF32 tensor cores --------
// Grid 2048 (one 128-row m-tile per block), 256 threads = 8 warps.
// Warp w computes rows [w*16, w*16+16) x all 128 n via mma.m16n8k8:
//   8 k-steps (K=64), 16 n-frags, 3 mma each (hh, hl, lh).
// X tile in smem (pad 68 -> conflict-free A-frag LDS). X loaded with .cg so
// W (read per-fragment via LDG) stays L1-resident.
__global__ __launch_bounds__(256)
void mdrnn_gemm_kernel(const float* __restrict__ X, const float* __restrict__ W,
                       const float* __restrict__ Bias, float* __restrict__ A) {
    __shared__ float xs[128 * 68];   // 34816 B

    const int tid   = threadIdx.x;
    const int mtile = blockIdx.x;
    const float* Xb = X + (size_t)mtile * 128 * PSIN;

    // load X tile 128x64: 2048 float4, 8 per thread, L1-bypass
#pragma unroll
    for (int q = 0; q < 8; q++) {
        int id  = tid + 256 * q;
        int row = id >> 4;          // 16 float4 per 64-float row
        int c4  = id & 15;
        float4 v = __ldcg((const float4*)(Xb + row * PSIN + c4 * 4));
        *(float4*)&xs[row * 68 + c4 * 4] = v;
    }
    __syncthreads();

    const int warp = tid >> 5;
    const int lane = tid & 31;
    const int g    = lane >> 2;     // 0..7
    const int t    = lane & 3;      // 0..3
    const int m0   = warp * 16;

    float acc[16][4];
#pragma unroll
    for (int nf = 0; nf < 16; nf++)
#pragma unroll
        for (int c = 0; c < 4; c++) acc[nf][c] = 0.f;

#pragma unroll
    for (int ks = 0; ks < 8; ks++) {
        const int kk = ks * 8;
        // A fragment (m16k8, row-major): a0:(g,t) a1:(g+8,t) a2:(g,t+4) a3:(g+8,t+4)
        float x0 = xs[(m0 + g)     * 68 + kk + t];
        float x1 = xs[(m0 + g + 8) * 68 + kk + t];
        float x2 = xs[(m0 + g)     * 68 + kk + t + 4];
        float x3 = xs[(m0 + g + 8) * 68 + kk + t + 4];
        uint32_t ah[4], al[4];
        split_tf32(x0, ah[0], al[0]);
        split_tf32(x1, ah[1], al[1]);
        split_tf32(x2, ah[2], al[2]);
        split_tf32(x3, ah[3], al[3]);

#pragma unroll
        for (int nf = 0; nf < 16; nf++) {
            // B fragment (k8n8): b0:(t, g) b1:(t+4, g), W row-major [k][n]
            float w0 = __ldg(W + (size_t)(kk + t)     * PSOUT + nf * 8 + g);
            float w1 = __ldg(W + (size_t)(kk + t + 4) * PSOUT + nf * 8 + g);
            uint32_t bh0, bl0, bh1, bl1;
            split_tf32(w0, bh0, bl0);
            split_tf32(w1, bh1, bl1);
            mma16n8k8(acc[nf], ah, bh0, bh1);   // hh
            mma16n8k8(acc[nf], ah, bl0, bl1);   // h*lo
            mma16n8k8(acc[nf], al, bh0, bh1);   // lo*h
        }
    }

    // epilogue: + bias, float2 stores
    const int row0 = mtile * 128 + m0 + g;
#pragma unroll
    for (int nf = 0; nf < 16; nf++) {
        int col = nf * 8 + 2 * t;
        float2 bv = *(const float2*)(Bias + col);
        float2 o0, o1;
        o0.x = acc[nf][0] + bv.x; o0.y = acc[nf][1] + bv.y;
        o1.x = acc[nf][2] + bv.x; o1.y = acc[nf][3] + bv.y;
        *(float2*)(A + (size_t)row0 * PSOUT + col)       = o0;
        *(float2*)(A + (size_t)(row0 + 8) * PSOUT + col) = o1;
    }
}

// ---------------- Kernel 2: 4-warp block wavefront scan ----------------
// Identical to R9 (134us) except tanh via single-MUFU tanh.approx.
#define SDEPTH 8
__global__ __launch_bounds__(128)
void mdrnn_scan_kernel(const float* __restrict__ U, float* __restrict__ H) {
    __shared__ float4 sha[2][128];
    __shared__ float4 shb[2][128];

    const int tid = threadIdx.x;            // row i
    const int b   = blockIdx.x >> 4;        // 0..15
    const int sc  = blockIdx.x & 15;        // 0..15
    const int s0  = sc * 8;

    const float4 u0a = *(const float4*)(U + s0);
    const float4 u0b = *(const float4*)(U + s0 + 4);
    const float4 u1a = *(const float4*)(U + PSOUT + s0);
    const float4 u1b = *(const float4*)(U + PSOUT + s0 + 4);

    float* Hrow = H + (size_t)tid * 262144 + (size_t)b * PSOUT + s0;  // + j*2048

    // seed ring: slot q <- a[j = q - tid] (consumed at t = q), valid j only
    float4 ra[SDEPTH], rb[SDEPTH];
#pragma unroll
    for (int q = 0; q < SDEPTH; q++) {
        int j = q - tid;
        if ((unsigned)j < 128u) {
            ra[q] = *(const float4*)(Hrow + (size_t)j * 2048);
            rb[q] = *(const float4*)(Hrow + (size_t)j * 2048 + 4);
        }
    }

    float4 ha = make_float4(0.f, 0.f, 0.f, 0.f);
    float4 hb = make_float4(0.f, 0.f, 0.f, 0.f);

#pragma unroll 8
    for (int t = 0; t < 256; t++) {
        const int j    = t - tid;
        const int slot = t & (SDEPTH - 1);   // static under unroll 8

        // consume slot, refill independent of this iter's activity
        float4 aa = ra[slot], ab = rb[slot];
        int jf = t + SDEPTH - tid;
        if ((unsigned)jf < 128u) {
            ra[slot] = *(const float4*)(Hrow + (size_t)jf * 2048);
            rb[slot] = *(const float4*)(Hrow + (size_t)jf * 2048 + 4);
        }

        if ((unsigned)j < 128u) {
            float4 qa, qb;   // h[i-1][j]
            if (tid == 0) {
                qa = make_float4(0.f, 0.f, 0.f, 0.f);
                qb = make_float4(0.f, 0.f, 0.f, 0.f);
            } else {
                qa = sha[(t & 1) ^ 1][tid - 1];
                qb = shb[(t & 1) ^ 1][tid - 1];
            }

            float4 za, zb;
            za.x = fmaf(qa.x, u0a.x, aa.x); za.x = fmaf(ha.x, u1a.x, za.x);
            za.y = fmaf(qa.y, u0a.y, aa.y); za.y = fmaf(ha.y, u1a.y, za.y);
            za.z = fmaf(qa.z, u0a.z, aa.z); za.z = fmaf(ha.z, u1a.z, za.z);
            za.w = fmaf(qa.w, u0a.w, aa.w); za.w = fmaf(ha.w, u1a.w, za.w);
            zb.x = fmaf(qb.x, u0b.x, ab.x); zb.x = fmaf(hb.x, u1b.x, zb.x);
            zb.y = fmaf(qb.y, u0b.y, ab.y); zb.y = fmaf(hb.y, u1b.y, zb.y);
            zb.z = fmaf(qb.z, u0b.z, ab.z); zb.z = fmaf(hb.z, u1b.z, zb.z);
            zb.w = fmaf(qb.w, u0b.w, ab.w); zb.w = fmaf(hb.w, u1b.w, zb.w);

            ha.x = tanh_mufu(za.x); ha.y = tanh_mufu(za.y);
            ha.z = tanh_mufu(za.z); ha.w = tanh_mufu(za.w);
            hb.x = tanh_mufu(zb.x); hb.y = tanh_mufu(zb.y);
            hb.z = tanh_mufu(zb.z); hb.w = tanh_mufu(zb.w);

            sha[t & 1][tid] = ha;
            shb[t & 1][tid] = hb;
            *(float4*)(Hrow + (size_t)j * 2048)     = ha;
            *(float4*)(Hrow + (size_t)j * 2048 + 4) = hb;
        }
        __syncthreads();
    }
}

// ---------------- launch ----------------
extern "C" void kernel_launch(void* const* d_in, const int* in_sizes, int n_in,
                              void* d_out, int out_size) {
    const float* X    = (const float*)d_in[0];   // (128,128,16,64)
    const float* W    = (const float*)d_in[1];   // (64,128)
    const float* U    = (const float*)d_in[2];   // (2,128)
    const float* Bias = (const float*)d_in[3];   // (128,)
    float* H = (float*)d_out;                    // (128,128,16,128) — holds a, then h

    (void)in_sizes; (void)n_in; (void)out_size;

    mdrnn_gemm_kernel<<<2048, 256>>>(X, W, Bias, H);
    mdrnn_scan_kernel<<<256, 128>>>(U, H);
}

// round 11
// speedup vs baseline: 1.3236x; 1.3236x over previous
#include <cuda_runtime.h>
#include <cstdint>

// Problem dims
#define PD1   128
#define PD2   128
#define PB    16
#define PSIN  64
#define PSOUT 128
// a / h layout: [i][j][b][s] row-major, s fastest.
// float offset = i*262144 + j*2048 + b*128 + s

typedef unsigned long long ull_t;

__device__ __forceinline__ ull_t pack2(float x) {
    unsigned int xi = __float_as_uint(x);
    ull_t r;
    asm("mov.b64 %0, {%1, %1};" : "=l"(r) : "r"(xi));
    return r;
}
__device__ __forceinline__ void ffma2(ull_t &d, ull_t a, ull_t b) {
    asm("fma.rn.f32x2 %0, %1, %2, %0;" : "+l"(d) : "l"(a), "l"(b));
}
__device__ __forceinline__ float tanh_mufu(float z) {
    float r;
    asm("tanh.approx.f32 %0, %1;" : "=f"(r) : "f"(z));
    return r;
}

// ---------------- Kernel 1: a = x @ w + bias  (into d_out) ----------------
// Measured ~91us (R7): 128m x 128n tile, 256 threads, micro-tile 8m x 8n
// (4 f32x2 segs), K=64 in two 32-wide phases. Reverted from TF32 (111us).
#define XS_LD 36
__global__ __launch_bounds__(256)
void mdrnn_gemm_kernel(const float* __restrict__ X, const float* __restrict__ W,
                       const float* __restrict__ Bias, float* __restrict__ A) {
    __shared__ float xs[128 * XS_LD];   // 18432 B
    __shared__ float ws[32 * 128];      // 16384 B

    const int tid   = threadIdx.x;
    const int mtile = blockIdx.x;                 // 2048 tiles of 128 rows
    const float* Xb = X + (size_t)mtile * 128 * PSIN;

    const int tidm = tid >> 4;
    const int tidn = tid & 15;
    const int m0   = tidm * 8;
    const int n0   = tidn * 2;

    ull_t acc[8][4];
#pragma unroll
    for (int mi = 0; mi < 8; mi++)
#pragma unroll
        for (int seg = 0; seg < 4; seg++) acc[mi][seg] = 0ULL;

    for (int kk = 0; kk < PSIN; kk += 32) {
        __syncthreads();
#pragma unroll
        for (int q = 0; q < 4; q++) {
            int id  = tid + 256 * q;
            int row = id >> 3;
            int kq  = id & 7;
            *(float4*)&xs[row * XS_LD + kq * 4] =
                *(const float4*)(Xb + row * PSIN + kk + kq * 4);
        }
#pragma unroll
        for (int q = 0; q < 4; q++) {
            int id = tid + 256 * q;
            int k  = id >> 5;
            int nq = id & 31;
            *(float4*)&ws[k * 128 + nq * 4] =
                *(const float4*)(W + (size_t)(kk + k) * PSOUT + nq * 4);
        }
        __syncthreads();

#pragma unroll 4
        for (int k = 0; k < 32; k++) {
            ull_t wv[4];
#pragma unroll
            for (int seg = 0; seg < 4; seg++)
                wv[seg] = *(const ull_t*)&ws[k * 128 + n0 + seg * 32];
#pragma unroll
            for (int mi = 0; mi < 8; mi++) {
                ull_t xp = pack2(xs[(m0 + mi) * XS_LD + k]);
#pragma unroll
                for (int seg = 0; seg < 4; seg++) ffma2(acc[mi][seg], xp, wv[seg]);
            }
        }
    }

    float2 bv[4];
#pragma unroll
    for (int seg = 0; seg < 4; seg++)
        bv[seg] = *(const float2*)(Bias + n0 + seg * 32);

#pragma unroll
    for (int mi = 0; mi < 8; mi++) {
        float* out = A + ((size_t)mtile * 128 + m0 + mi) * PSOUT;
#pragma unroll
        for (int seg = 0; seg < 4; seg++) {
            uint2 u = *(uint2*)&acc[mi][seg];
            float2 o;
            o.x = __uint_as_float(u.x) + bv[seg].x;
            o.y = __uint_as_float(u.y) + bv[seg].y;
            *(float2*)(out + n0 + seg * 32) = o;
        }
    }
}

// ---------------- Kernel 2: 8-warp wavefront scan, 2 threads/row ------------
// 128 blocks x 256 threads. Block = (b, 16-wide s chunk).
// Thread = (row i = tid>>1, 8-s half = tid&1): adjacent lanes cover 64B
// contiguous per row -> each LDG.128/STG.128 touches 16 lines (not 32),
// halving total L1 wavefronts vs R9/R10 (which this model showed to be the
// binding constraint: ~512 wf/block-step ~= measured ~1000cyc/step at
// 2 blocks/L1). At 128 blocks every SM holds at most one block.
// 256 diagonal steps; h[i-1][j] via double-buffered smem + __syncthreads.
// Prefetch ring depth 8, STATIC indices (unroll 8); refill guarded only
// by jf validity (activity-independent).
#define SDEPTH 8
__global__ __launch_bounds__(256)
void mdrnn_scan_kernel(const float* __restrict__ U, float* __restrict__ H) {
    __shared__ float4 sha[2][128][2];   // [buf][row][half], 8KB
    __shared__ float4 shb[2][128][2];   // 8KB

    const int tid  = threadIdx.x;
    const int i    = tid >> 1;           // row 0..127
    const int half = tid & 1;            // 0..1
    const int b    = blockIdx.x >> 3;    // 0..15
    const int sc   = blockIdx.x & 7;     // 0..7
    const int s0   = sc * 16 + half * 8; // global s of this thread's 8 floats

    const float4 u0a = *(const float4*)(U + s0);
    const float4 u0b = *(const float4*)(U + s0 + 4);
    const float4 u1a = *(const float4*)(U + PSOUT + s0);
    const float4 u1b = *(const float4*)(U + PSOUT + s0 + 4);

    float* Hrow = H + (size_t)i * 262144 + (size_t)b * PSOUT + s0;  // + j*2048

    // seed ring: slot q <- a[j = q - i] (consumed at t = q), valid j only
    float4 ra[SDEPTH], rb[SDEPTH];
#pragma unroll
    for (int q = 0; q < SDEPTH; q++) {
        int j = q - i;
        if ((unsigned)j < 128u) {
            ra[q] = *(const float4*)(Hrow + (size_t)j * 2048);
            rb[q] = *(const float4*)(Hrow + (size_t)j * 2048 + 4);
        }
    }

    float4 ha = make_float4(0.f, 0.f, 0.f, 0.f);
    float4 hb = make_float4(0.f, 0.f, 0.f, 0.f);

#pragma unroll 8
    for (int t = 0; t < 256; t++) {
        const int j    = t - i;
        const int slot = t & (SDEPTH - 1);   // static under unroll 8

        // consume slot, refill independent of this iter's activity
        float4 aa = ra[slot], ab = rb[slot];
        int jf = t + SDEPTH - i;
        if ((unsigned)jf < 128u) {
            ra[slot] = *(const float4*)(Hrow + (size_t)jf * 2048);
            rb[slot] = *(const float4*)(Hrow + (size_t)jf * 2048 + 4);
        }

        if ((unsigned)j < 128u) {
            float4 qa, qb;   // h[i-1][j] (same half)
            if (i == 0) {
                qa = make_float4(0.f, 0.f, 0.f, 0.f);
                qb = make_float4(0.f, 0.f, 0.f, 0.f);
            } else {
                qa = sha[(t & 1) ^ 1][i - 1][half];
                qb = shb[(t & 1) ^ 1][i - 1][half];
            }

            float4 za, zb;
            za.x = fmaf(qa.x, u0a.x, aa.x); za.x = fmaf(ha.x, u1a.x, za.x);
            za.y = fmaf(qa.y, u0a.y, aa.y); za.y = fmaf(ha.y, u1a.y, za.y);
            za.z = fmaf(qa.z, u0a.z, aa.z); za.z = fmaf(ha.z, u1a.z, za.z);
            za.w = fmaf(qa.w, u0a.w, aa.w); za.w = fmaf(ha.w, u1a.w, za.w);
            zb.x = fmaf(qb.x, u0b.x, ab.x); zb.x = fmaf(hb.x, u1b.x, zb.x);
            zb.y = fmaf(qb.y, u0b.y, ab.y); zb.y = fmaf(hb.y, u1b.y, zb.y);
            zb.z = fmaf(qb.z, u0b.z, ab.z); zb.z = fmaf(hb.z, u1b.z, zb.z);
            zb.w = fmaf(qb.w, u0b.w, ab.w); zb.w = fmaf(hb.w, u1b.w, zb.w);

            ha.x = tanh_mufu(za.x); ha.y = tanh_mufu(za.y);
            ha.z = tanh_mufu(za.z); ha.w = tanh_mufu(za.w);
            hb.x = tanh_mufu(zb.x); hb.y = tanh_mufu(zb.y);
            hb.z = tanh_mufu(zb.z); hb.w = tanh_mufu(zb.w);

            sha[t & 1][i][half] = ha;
            shb[t & 1][i][half] = hb;
            *(float4*)(Hrow + (size_t)j * 2048)     = ha;
            *(float4*)(Hrow + (size_t)j * 2048 + 4) = hb;
        }
        __syncthreads();
    }
}

// ---------------- launch ----------------
extern "C" void kernel_launch(void* const* d_in, const int* in_sizes, int n_in,
                              void* d_out, int out_size) {
    const float* X    = (const float*)d_in[0];   // (128,128,16,64)
    const float* W    = (const float*)d_in[1];   // (64,128)
    const float* U    = (const float*)d_in[2];   // (2,128)
    const float* Bias = (const float*)d_in[3];   // (128,)
    float* H = (float*)d_out;                    // (128,128,16,128) — holds a, then h

    (void)in_sizes; (void)n_in; (void)out_size;

    mdrnn_gemm_kernel<<<2048, 256>>>(X, W, Bias, H);
    mdrnn_scan_kernel<<<128, 256>>>(U, H);
}

// round 12
// speedup vs baseline: 1.4379x; 1.0863x over previous
#include <cuda_runtime.h>
#include <cstdint>

// Problem dims
#define PD1   128
#define PD2   128
#define PB    16
#define PSIN  64
#define PSOUT 128
// a / h layout: [i][j][b][s] row-major, s fastest.
// float offset = i*262144 + j*2048 + b*128 + s

typedef unsigned long long ull_t;

__device__ __forceinline__ ull_t pack2(float x) {
    unsigned int xi = __float_as_uint(x);
    ull_t r;
    asm("mov.b64 %0, {%1, %1};" : "=l"(r) : "r"(xi));
    return r;
}
__device__ __forceinline__ void ffma2(ull_t &d, ull_t a, ull_t b) {
    asm("fma.rn.f32x2 %0, %1, %2, %0;" : "+l"(d) : "l"(a), "l"(b));
}
__device__ __forceinline__ float tanh_mufu(float z) {
    float r;
    asm("tanh.approx.f32 %0, %1;" : "=f"(r) : "f"(z));
    return r;
}

// ---------------- Kernel 1: a = x @ w + bias  (into d_out) ----------------
// Measured ~91us (R7): 128m x 128n tile, 256 threads, micro-tile 8m x 8n
// (4 f32x2 segs), K=64 in two 32-wide phases. Unchanged.
#define XS_LD 36
__global__ __launch_bounds__(256)
void mdrnn_gemm_kernel(const float* __restrict__ X, const float* __restrict__ W,
                       const float* __restrict__ Bias, float* __restrict__ A) {
    __shared__ float xs[128 * XS_LD];   // 18432 B
    __shared__ float ws[32 * 128];      // 16384 B

    const int tid   = threadIdx.x;
    const int mtile = blockIdx.x;                 // 2048 tiles of 128 rows
    const float* Xb = X + (size_t)mtile * 128 * PSIN;

    const int tidm = tid >> 4;
    const int tidn = tid & 15;
    const int m0   = tidm * 8;
    const int n0   = tidn * 2;

    ull_t acc[8][4];
#pragma unroll
    for (int mi = 0; mi < 8; mi++)
#pragma unroll
        for (int seg = 0; seg < 4; seg++) acc[mi][seg] = 0ULL;

    for (int kk = 0; kk < PSIN; kk += 32) {
        __syncthreads();
#pragma unroll
        for (int q = 0; q < 4; q++) {
            int id  = tid + 256 * q;
            int row = id >> 3;
            int kq  = id & 7;
            *(float4*)&xs[row * XS_LD + kq * 4] =
                *(const float4*)(Xb + row * PSIN + kk + kq * 4);
        }
#pragma unroll
        for (int q = 0; q < 4; q++) {
            int id = tid + 256 * q;
            int k  = id >> 5;
            int nq = id & 31;
            *(float4*)&ws[k * 128 + nq * 4] =
                *(const float4*)(W + (size_t)(kk + k) * PSOUT + nq * 4);
        }
        __syncthreads();

#pragma unroll 4
        for (int k = 0; k < 32; k++) {
            ull_t wv[4];
#pragma unroll
            for (int seg = 0; seg < 4; seg++)
                wv[seg] = *(const ull_t*)&ws[k * 128 + n0 + seg * 32];
#pragma unroll
            for (int mi = 0; mi < 8; mi++) {
                ull_t xp = pack2(xs[(m0 + mi) * XS_LD + k]);
#pragma unroll
                for (int seg = 0; seg < 4; seg++) ffma2(acc[mi][seg], xp, wv[seg]);
            }
        }
    }

    float2 bv[4];
#pragma unroll
    for (int seg = 0; seg < 4; seg++)
        bv[seg] = *(const float2*)(Bias + n0 + seg * 32);

#pragma unroll
    for (int mi = 0; mi < 8; mi++) {
        float* out = A + ((size_t)mtile * 128 + m0 + mi) * PSOUT;
#pragma unroll
        for (int seg = 0; seg < 4; seg++) {
            uint2 u = *(uint2*)&acc[mi][seg];
            float2 o;
            o.x = __uint_as_float(u.x) + bv[seg].x;
            o.y = __uint_as_float(u.y) + bv[seg].y;
            *(float2*)(out + n0 + seg * 32) = o;
        }
    }
}

// ---------------- Kernel 2: 16-warp wavefront scan, 4 threads/row -----------
// 128 blocks x 512 threads. Block = (b, 16-wide s chunk).
// Thread = (row i = tid>>2, s-quad = tid&3): one float4 per thread, 4 lanes
// cover 64B contiguous per row -> ONE LDG.128 + ONE STG.128 per thread-step
// (vs R11's 2+2) and 8 line-wavefronts per instruction. Per warp-step: 16 wf
// (was 64) -> total L1 wavefronts halved again.
// 256 diagonal steps; h[i-1][j] via double-buffered smem + __syncthreads.
// Prefetch ring depth 8, STATIC indices (unroll 8); refill guarded only
// by jf validity (activity-independent).
#define SDEPTH 8
__global__ __launch_bounds__(512)
void mdrnn_scan_kernel(const float* __restrict__ U, float* __restrict__ H) {
    __shared__ float4 sh[2][128][4];   // [buf][row][quad], 16KB

    const int tid = threadIdx.x;
    const int i   = tid >> 2;            // row 0..127
    const int qd  = tid & 3;             // s-quad 0..3
    const int b   = blockIdx.x >> 3;     // 0..15
    const int sc  = blockIdx.x & 7;      // 0..7
    const int s0  = sc * 16 + qd * 4;    // global s of this thread's 4 floats

    const float4 u0 = *(const float4*)(U + s0);
    const float4 u1 = *(const float4*)(U + PSOUT + s0);

    float* Hrow = H + (size_t)i * 262144 + (size_t)b * PSOUT + s0;  // + j*2048

    // seed ring: slot q <- a[j = q - i] (consumed at t = q), valid j only
    float4 ra[SDEPTH];
#pragma unroll
    for (int q = 0; q < SDEPTH; q++) {
        int j = q - i;
        if ((unsigned)j < 128u)
            ra[q] = *(const float4*)(Hrow + (size_t)j * 2048);
    }

    float4 h = make_float4(0.f, 0.f, 0.f, 0.f);   // this row's h, prev column

#pragma unroll 8
    for (int t = 0; t < 256; t++) {
        const int j    = t - i;
        const int slot = t & (SDEPTH - 1);   // static under unroll 8

        // consume slot, refill independent of this iter's activity
        float4 aa = ra[slot];
        int jf = t + SDEPTH - i;
        if ((unsigned)jf < 128u)
            ra[slot] = *(const float4*)(Hrow + (size_t)jf * 2048);

        if ((unsigned)j < 128u) {
            float4 qa;   // h[i-1][j], same quad
            if (i == 0) {
                qa = make_float4(0.f, 0.f, 0.f, 0.f);
            } else {
                qa = sh[(t & 1) ^ 1][i - 1][qd];
            }

            float4 z;
            z.x = fmaf(qa.x, u0.x, aa.x); z.x = fmaf(h.x, u1.x, z.x);
            z.y = fmaf(qa.y, u0.y, aa.y); z.y = fmaf(h.y, u1.y, z.y);
            z.z = fmaf(qa.z, u0.z, aa.z); z.z = fmaf(h.z, u1.z, z.z);
            z.w = fmaf(qa.w, u0.w, aa.w); z.w = fmaf(h.w, u1.w, z.w);

            h.x = tanh_mufu(z.x); h.y = tanh_mufu(z.y);
            h.z = tanh_mufu(z.z); h.w = tanh_mufu(z.w);

            sh[t & 1][i][qd] = h;
            *(float4*)(Hrow + (size_t)j * 2048) = h;
        }
        __syncthreads();
    }
}

// ---------------- launch ----------------
extern "C" void kernel_launch(void* const* d_in, const int* in_sizes, int n_in,
                              void* d_out, int out_size) {
    const float* X    = (const float*)d_in[0];   // (128,128,16,64)
    const float* W    = (const float*)d_in[1];   // (64,128)
    const float* U    = (const float*)d_in[2];   // (2,128)
    const float* Bias = (const float*)d_in[3];   // (128,)
    float* H = (float*)d_out;                    // (128,128,16,128) — holds a, then h

    (void)in_sizes; (void)n_in; (void)out_size;

    mdrnn_gemm_kernel<<<2048, 256>>>(X, W, Bias, H);
    mdrnn_scan_kernel<<<128, 512>>>(U, H);
}

// round 13
// speedup vs baseline: 1.4420x; 1.0029x over previous
#include <cuda_runtime.h>
#include <cstdint>

// Problem dims
#define PD1   128
#define PD2   128
#define PB    16
#define PSIN  64
#define PSOUT 128
// a / h layout: [i][j][b][s] row-major, s fastest.
// float offset = i*262144 + j*2048 + b*128 + s

__device__ __forceinline__ float tanh_mufu(float z) {
    float r;
    asm("tanh.approx.f32 %0, %1;" : "=f"(r) : "f"(z));
    return r;
}
// split fp32 into tf32 hi + tf32 lo (3xTF32 trick)
__device__ __forceinline__ void split_tf32(float x, uint32_t &hi, uint32_t &lo) {
    asm("cvt.rna.tf32.f32 %0, %1;" : "=r"(hi) : "f"(x));
    float r = x - __uint_as_float(hi);
    asm("cvt.rna.tf32.f32 %0, %1;" : "=r"(lo) : "f"(r));
}
__device__ __forceinline__ void mma16n8k8(float* d, const uint32_t* a,
                                          uint32_t b0, uint32_t b1) {
    asm("mma.sync.aligned.m16n8k8.row.col.f32.tf32.tf32.f32 "
        "{%0,%1,%2,%3}, {%4,%5,%6,%7}, {%8,%9}, {%0,%1,%2,%3};"
        : "+f"(d[0]), "+f"(d[1]), "+f"(d[2]), "+f"(d[3])
        : "r"(a[0]), "r"(a[1]), "r"(a[2]), "r"(a[3]), "r"(b0), "r"(b1));
}

// ---------------- Kernel 1: a = x @ w + bias, 3xTF32, all-smem operands -----
// Grid 2048 x 256 threads (8 warps). Warp w: rows [w*16, w*16+16) x n=128.
// Dynamic smem layout (floats):
//   xs  [0      .. 8704)  : X tile 128 x 68  (stride 68 -> A-frag LDS spreads
//                           banks as 4g+t, all 32 lanes distinct)
//   whi [8704   .. 17408) : W hi tf32, 64 x 136 (stride 136: 136%32=8 ->
//                           B-frag LDS banks 8t+g, all 32 lanes distinct)
//   wlo [17408  .. 26112) : W lo tf32, same layout
// Total 26112 floats = 104448 B (needs cudaFuncSetAttribute).
// Fragment layouts identical to R10 (verified correct by its passing run).
__global__ __launch_bounds__(256)
void mdrnn_gemm_kernel(const float* __restrict__ X, const float* __restrict__ W,
                       const float* __restrict__ Bias, float* __restrict__ A) {
    extern __shared__ float smem[];
    float*    xs  = smem;              // 128 x 68
    uint32_t* whi = (uint32_t*)(smem + 8704);    // 64 x 136
    uint32_t* wlo = (uint32_t*)(smem + 17408);   // 64 x 136

    const int tid   = threadIdx.x;
    const int mtile = blockIdx.x;
    const float* Xb = X + (size_t)mtile * 128 * PSIN;

    // stage X tile: 2048 float4, 8 per thread (L1-bypass; streamed once)
#pragma unroll
    for (int q = 0; q < 8; q++) {
        int id  = tid + 256 * q;
        int row = id >> 4;
        int c4  = id & 15;
        float4 v = __ldcg((const float4*)(Xb + row * PSIN + c4 * 4));
        *(float4*)&xs[row * 68 + c4 * 4] = v;
    }
    // stage + split W: 64x128 floats = 2048 float4, 8 per thread
#pragma unroll
    for (int q = 0; q < 8; q++) {
        int id  = tid + 256 * q;
        int k   = id >> 5;           // 32 float4 per 128-float row
        int c4  = id & 31;
        float4 v = *(const float4*)(W + (size_t)k * PSOUT + c4 * 4);
        uint32_t h0, l0, h1, l1, h2, l2, h3, l3;
        split_tf32(v.x, h0, l0); split_tf32(v.y, h1, l1);
        split_tf32(v.z, h2, l2); split_tf32(v.w, h3, l3);
        uint32_t* ph = &whi[k * 136 + c4 * 4];
        uint32_t* pl = &wlo[k * 136 + c4 * 4];
        ph[0] = h0; ph[1] = h1; ph[2] = h2; ph[3] = h3;
        pl[0] = l0; pl[1] = l1; pl[2] = l2; pl[3] = l3;
    }
    __syncthreads();

    const int warp = tid >> 5;
    const int lane = tid & 31;
    const int g    = lane >> 2;     // 0..7
    const int t    = lane & 3;      // 0..3
    const int m0   = warp * 16;

    float acc[16][4];
#pragma unroll
    for (int nf = 0; nf < 16; nf++)
#pragma unroll
        for (int c = 0; c < 4; c++) acc[nf][c] = 0.f;

#pragma unroll
    for (int ks = 0; ks < 8; ks++) {
        const int kk = ks * 8;
        // A fragment (m16k8 row-major): a0:(g,t) a1:(g+8,t) a2:(g,t+4) a3:(g+8,t+4)
        float x0 = xs[(m0 + g)     * 68 + kk + t];
        float x1 = xs[(m0 + g + 8) * 68 + kk + t];
        float x2 = xs[(m0 + g)     * 68 + kk + t + 4];
        float x3 = xs[(m0 + g + 8) * 68 + kk + t + 4];
        uint32_t ah[4], al[4];
        split_tf32(x0, ah[0], al[0]);
        split_tf32(x1, ah[1], al[1]);
        split_tf32(x2, ah[2], al[2]);
        split_tf32(x3, ah[3], al[3]);

        const int r0 = (kk + t) * 136;
        const int r1 = (kk + t + 4) * 136;
#pragma unroll
        for (int nf = 0; nf < 16; nf++) {
            // B fragment (k8n8 col-major): b0:(t, g) b1:(t+4, g)
            uint32_t bh0 = whi[r0 + nf * 8 + g];
            uint32_t bh1 = whi[r1 + nf * 8 + g];
            uint32_t bl0 = wlo[r0 + nf * 8 + g];
            uint32_t bl1 = wlo[r1 + nf * 8 + g];
            mma16n8k8(acc[nf], ah, bh0, bh1);   // hi*hi
            mma16n8k8(acc[nf], ah, bl0, bl1);   // hi*lo
            mma16n8k8(acc[nf], al, bh0, bh1);   // lo*hi
        }
    }

    // epilogue: + bias, float2 stores (layout verified in R10)
    const int row0 = mtile * 128 + m0 + g;
#pragma unroll
    for (int nf = 0; nf < 16; nf++) {
        int col = nf * 8 + 2 * t;
        float2 bv = *(const float2*)(Bias + col);
        float2 o0, o1;
        o0.x = acc[nf][0] + bv.x; o0.y = acc[nf][1] + bv.y;
        o1.x = acc[nf][2] + bv.x; o1.y = acc[nf][3] + bv.y;
        *(float2*)(A + (size_t)row0 * PSOUT + col)       = o0;
        *(float2*)(A + (size_t)(row0 + 8) * PSOUT + col) = o1;
    }
}

// ---------------- Kernel 2: 16-warp wavefront scan, 4 threads/row -----------
// Identical to R12 (measured 71.8us).
#define SDEPTH 8
__global__ __launch_bounds__(512)
void mdrnn_scan_kernel(const float* __restrict__ U, float* __restrict__ H) {
    __shared__ float4 sh[2][128][4];   // [buf][row][quad], 16KB

    const int tid = threadIdx.x;
    const int i   = tid >> 2;            // row 0..127
    const int qd  = tid & 3;             // s-quad 0..3
    const int b   = blockIdx.x >> 3;     // 0..15
    const int sc  = blockIdx.x & 7;      // 0..7
    const int s0  = sc * 16 + qd * 4;

    const float4 u0 = *(const float4*)(U + s0);
    const float4 u1 = *(const float4*)(U + PSOUT + s0);

    float* Hrow = H + (size_t)i * 262144 + (size_t)b * PSOUT + s0;  // + j*2048

    float4 ra[SDEPTH];
#pragma unroll
    for (int q = 0; q < SDEPTH; q++) {
        int j = q - i;
        if ((unsigned)j < 128u)
            ra[q] = *(const float4*)(Hrow + (size_t)j * 2048);
    }

    float4 h = make_float4(0.f, 0.f, 0.f, 0.f);

#pragma unroll 8
    for (int t = 0; t < 256; t++) {
        const int j    = t - i;
        const int slot = t & (SDEPTH - 1);

        float4 aa = ra[slot];
        int jf = t + SDEPTH - i;
        if ((unsigned)jf < 128u)
            ra[slot] = *(const float4*)(Hrow + (size_t)jf * 2048);

        if ((unsigned)j < 128u) {
            float4 qa;
            if (i == 0) {
                qa = make_float4(0.f, 0.f, 0.f, 0.f);
            } else {
                qa = sh[(t & 1) ^ 1][i - 1][qd];
            }

            float4 z;
            z.x = fmaf(qa.x, u0.x, aa.x); z.x = fmaf(h.x, u1.x, z.x);
            z.y = fmaf(qa.y, u0.y, aa.y); z.y = fmaf(h.y, u1.y, z.y);
            z.z = fmaf(qa.z, u0.z, aa.z); z.z = fmaf(h.z, u1.z, z.z);
            z.w = fmaf(qa.w, u0.w, aa.w); z.w = fmaf(h.w, u1.w, z.w);

            h.x = tanh_mufu(z.x); h.y = tanh_mufu(z.y);
            h.z = tanh_mufu(z.z); h.w = tanh_mufu(z.w);

            sh[t & 1][i][qd] = h;
            *(float4*)(Hrow + (size_t)j * 2048) = h;
        }
        __syncthreads();
    }
}

// ---------------- launch ----------------
extern "C" void kernel_launch(void* const* d_in, const int* in_sizes, int n_in,
                              void* d_out, int out_size) {
    const float* X    = (const float*)d_in[0];   // (128,128,16,64)
    const float* W    = (const float*)d_in[1];   // (64,128)
    const float* U    = (const float*)d_in[2];   // (2,128)
    const float* Bias = (const float*)d_in[3];   // (128,)
    float* H = (float*)d_out;                    // (128,128,16,128) — holds a, then h

    (void)in_sizes; (void)n_in; (void)out_size;

    const int gemm_smem = 26112 * 4;   // 104448 B dynamic smem
    cudaFuncSetAttribute(mdrnn_gemm_kernel,
                         cudaFuncAttributeMaxDynamicSharedMemorySize, gemm_smem);

    mdrnn_gemm_kernel<<<2048, 256, gemm_smem>>>(X, W, Bias, H);
    mdrnn_scan_kernel<<<128, 512>>>(U, H);
}